// round 12
// baseline (speedup 1.0000x reference)
#include <cuda_runtime.h>

#define KS     5
#define TAPS   25
#define NKP    13          // k-pairs (k=25: pair 12 lane1 zero-padded)
#define CCH    3
#define HALO   2
#define TILE_W 32
#define TILE_H 8
#define RPT    2           // pixels (rows) per thread
#define SM_W   (TILE_W + 2*HALO)   // 36
#define SM_H   (TILE_H + 2*HALO)   // 12
#define NTHREADS 128

typedef unsigned long long u64;

__device__ __forceinline__ u64 pack2(float lo, float hi) {
    u64 r;
    asm("mov.b64 %0, {%1, %2};" : "=l"(r) : "f"(lo), "f"(hi));
    return r;
}
__device__ __forceinline__ void unpack2(u64 v, float& lo, float& hi) {
    asm("mov.b64 {%0, %1}, %2;" : "=f"(lo), "=f"(hi) : "l"(v));
}
__device__ __forceinline__ void ffma2(u64& d, u64 a, u64 b) {
    asm("fma.rn.f32x2 %0, %1, %2, %0;" : "+l"(d) : "l"(a), "l"(b));
}

__global__ void __launch_bounds__(NTHREADS, 5)
ho_kpair5_kernel(const float* __restrict__ x,
                 const float* __restrict__ cw,   // [25][3][5][5]
                 const float* __restrict__ cb,   // [25]
                 float* __restrict__ out,
                 int H, int W)
{
    // Tile stored LANE-DUPLICATED: s_dup[idx] = (v, v). Pass-1 n-operand = one LDS.64.
    __shared__ u64 s_dup[CCH * SM_H * SM_W];          // 1296 u64 = 10.4 KB
    __shared__ u64 s_w2[CCH * TAPS * NKP];            // [(c*25+m)*13+kp] = 7.8 KB
    __shared__ u64 s_b2[NKP];

    const int tid = threadIdx.x;

    // Stage weights as k-pairs: s_w2[(c*25+m)*13+kp] = (cw[2kp][c][m], cw[2kp+1][c][m])
    for (int idx = tid; idx < CCH * TAPS * NKP; idx += NTHREADS) {
        int c   = idx / (TAPS * NKP);
        int rem = idx % (TAPS * NKP);
        int m   = rem / NKP;
        int kp  = rem % NKP;
        int k0 = 2 * kp, k1 = k0 + 1;
        float w0 = cw[(k0 * CCH + c) * TAPS + m];
        float w1 = (k1 < TAPS) ? cw[(k1 * CCH + c) * TAPS + m] : 0.0f;
        s_w2[idx] = pack2(w0, w1);
    }
    if (tid < NKP) {
        int k0 = 2 * tid, k1 = k0 + 1;
        s_b2[tid] = pack2(cb[k0], (k1 < TAPS) ? cb[k1] : 0.0f);
    }

    const int b  = blockIdx.z;
    const int h0 = blockIdx.y * TILE_H;
    const int w0 = blockIdx.x * TILE_W;
    const float* xb = x + (size_t)b * CCH * H * W;

    // Stage input tile + halo, duplicated into both lanes
    for (int i = tid; i < CCH * SM_H * SM_W; i += NTHREADS) {
        int c   = i / (SM_H * SM_W);
        int r   = (i / SM_W) % SM_H;
        int col = i % SM_W;
        int hh = h0 + r   - HALO;
        int ww = w0 + col - HALO;
        float v = 0.0f;
        if (hh >= 0 && hh < H && ww >= 0 && ww < W)
            v = xb[(size_t)c * H * W + (size_t)hh * W + ww];
        s_dup[i] = pack2(v, v);
    }
    __syncthreads();

    const int tx = tid & 31;          // 0..31
    const int ty = tid >> 5;          // 0..3
    const int ry = ty * RPT;          // top pixel's tile-local row

    // ---- Pass 1: dynamic weights packed along k:
    //      wacc[p][kp] = (w_{2kp}(pixel p), w_{2kp+1}(pixel p))
    u64 wacc[RPT][NKP];
#pragma unroll
    for (int p = 0; p < RPT; p++)
#pragma unroll
        for (int q = 0; q < NKP; q++)
            wacc[p][q] = s_b2[q];

#pragma unroll
    for (int c = 0; c < CCH; c++) {
#pragma unroll
        for (int m = 0; m < TAPS; m++) {
            const int i = m / KS, j = m % KS;
            u64 nd0 = s_dup[(c * SM_H + ry + i    ) * SM_W + tx + j];   // (v,v)
            u64 nd1 = s_dup[(c * SM_H + ry + i + 1) * SM_W + tx + j];
            const u64* wp = &s_w2[(c * TAPS + m) * NKP];
#pragma unroll
            for (int q = 0; q < NKP; q++) {
                u64 wv = wp[q];                  // one LDS.64: two distinct weights
                ffma2(wacc[0][q], wv, nd0);
                ffma2(wacc[1][q], wv, nd1);
            }
        }
    }

    // ---- Pass 2: fold k-pairs into packed output (lane-split sums), horizontal-add
    float* ob = out + (size_t)b * CCH * H * W;
    const int h = h0 + ry;
    const int w = w0 + tx;

#pragma unroll
    for (int c = 0; c < CCH; c++) {
        u64 acc[RPT];
#pragma unroll
        for (int p = 0; p < RPT; p++) {
            float rlo, rhi;
            unpack2(s_dup[(c * SM_H + ry + p + HALO) * SM_W + tx + HALO], rlo, rhi);
            acc[p] = pack2(rlo, 0.0f);           // residual in lane0
        }

#pragma unroll
        for (int q = 0; q < NKP; q++) {
            const int k0 = 2 * q, k1 = k0 + 1;
            const int i0 = k0 / KS, j0 = k0 % KS;
            const int i1 = (k1 < TAPS) ? k1 / KS : 0;
            const int j1 = (k1 < TAPS) ? k1 % KS : 0;
#pragma unroll
            for (int p = 0; p < RPT; p++) {
                float n0, n0x, n1x, n1;
                unpack2(s_dup[(c * SM_H + ry + p + i0) * SM_W + tx + j0], n0, n0x);
                if (k1 < TAPS) {
                    unpack2(s_dup[(c * SM_H + ry + p + i1) * SM_W + tx + j1], n1x, n1);
                } else {
                    n1 = 0.0f;
                }
                ffma2(acc[p], wacc[p][q], pack2(n0, n1));
            }
        }

        float* op = ob + (size_t)c * H * W + (size_t)h * W + w;
#pragma unroll
        for (int p = 0; p < RPT; p++) {
            float lo, hi;
            unpack2(acc[p], lo, hi);
            op[(size_t)p * W] = lo + hi;
        }
    }
}

extern "C" void kernel_launch(void* const* d_in, const int* in_sizes, int n_in,
                              void* d_out, int out_size)
{
    const float* x  = (const float*)d_in[0];
    const float* cw = (const float*)d_in[1];
    const float* cb = (const float*)d_in[2];
    float* out      = (float*)d_out;

    const int H = 256, W = 256;
    const int B = in_sizes[0] / (CCH * H * W);   // 16

    dim3 grid(W / TILE_W, H / TILE_H, B);        // (8, 32, 16) = 4096 blocks
    ho_kpair5_kernel<<<grid, NTHREADS>>>(x, cw, cb, out, H, W);
}

// round 14
// speedup vs baseline: 1.9299x; 1.9299x over previous
#include <cuda_runtime.h>

#define KS     5
#define TAPS   25
#define NKP    13          // k-pairs (k=25: pair 12 lane1 zero-padded)
#define CCH    3
#define HALO   2
#define TILE_W 32
#define TILE_H 16
#define RPT    2           // pixels (rows) per thread
#define SM_W   (TILE_W + 2*HALO)   // 36
#define SM_H   (TILE_H + 2*HALO)   // 20
#define NTHREADS 256

typedef unsigned long long u64;

__device__ __forceinline__ u64 pack2(float lo, float hi) {
    u64 r;
    asm("mov.b64 %0, {%1, %2};" : "=l"(r) : "f"(lo), "f"(hi));
    return r;
}
__device__ __forceinline__ void unpack2(u64 v, float& lo, float& hi) {
    asm("mov.b64 {%0, %1}, %2;" : "=f"(lo), "=f"(hi) : "l"(v));
}
__device__ __forceinline__ void ffma2(u64& d, u64 a, u64 b) {
    asm("fma.rn.f32x2 %0, %1, %2, %0;" : "+l"(d) : "l"(a), "l"(b));
}

__global__ void __launch_bounds__(NTHREADS, 2)
ho_kpair6_kernel(const float* __restrict__ x,
                 const float* __restrict__ cw,   // [25][3][5][5]
                 const float* __restrict__ cb,   // [25]
                 float* __restrict__ out,
                 int H, int W)
{
    // Tile stored LANE-DUPLICATED: s_dup[idx] = (v, v).
    // Pass-1 n-operand = one LDS.64 straight into an aligned register pair (no pack MOVs).
    __shared__ u64 s_dup[CCH * SM_H * SM_W];          // 2160 u64 = 17.3 KB
    __shared__ u64 s_w2[CCH * TAPS * NKP];            // [(c*25+m)*13+kp] = 7.8 KB
    __shared__ u64 s_b2[NKP];

    const int tid = threadIdx.x;

    // Stage weights as k-pairs: s_w2[(c*25+m)*13+kp] = (cw[2kp][c][m], cw[2kp+1][c][m])
    for (int idx = tid; idx < CCH * TAPS * NKP; idx += NTHREADS) {
        int c   = idx / (TAPS * NKP);
        int rem = idx % (TAPS * NKP);
        int m   = rem / NKP;
        int kp  = rem % NKP;
        int k0 = 2 * kp, k1 = k0 + 1;
        float w0 = cw[(k0 * CCH + c) * TAPS + m];
        float w1 = (k1 < TAPS) ? cw[(k1 * CCH + c) * TAPS + m] : 0.0f;
        s_w2[idx] = pack2(w0, w1);
    }
    if (tid < NKP) {
        int k0 = 2 * tid, k1 = k0 + 1;
        s_b2[tid] = pack2(cb[k0], (k1 < TAPS) ? cb[k1] : 0.0f);
    }

    const int b  = blockIdx.z;
    const int h0 = blockIdx.y * TILE_H;
    const int w0 = blockIdx.x * TILE_W;
    const float* xb = x + (size_t)b * CCH * H * W;

    // Stage input tile + halo, duplicated into both lanes
    for (int i = tid; i < CCH * SM_H * SM_W; i += NTHREADS) {
        int c   = i / (SM_H * SM_W);
        int r   = (i / SM_W) % SM_H;
        int col = i % SM_W;
        int hh = h0 + r   - HALO;
        int ww = w0 + col - HALO;
        float v = 0.0f;
        if (hh >= 0 && hh < H && ww >= 0 && ww < W)
            v = xb[(size_t)c * H * W + (size_t)hh * W + ww];
        s_dup[i] = pack2(v, v);
    }
    __syncthreads();

    const int tx = tid & 31;          // 0..31
    const int ty = tid >> 5;          // 0..7
    const int ry = ty * RPT;          // top pixel's tile-local row

    // ---- Pass 1: dynamic weights packed along k:
    //      wacc[p][kp] = (w_{2kp}(pixel p), w_{2kp+1}(pixel p))
    u64 wacc[RPT][NKP];
#pragma unroll
    for (int p = 0; p < RPT; p++)
#pragma unroll
        for (int q = 0; q < NKP; q++)
            wacc[p][q] = s_b2[q];

#pragma unroll
    for (int c = 0; c < CCH; c++) {
#pragma unroll
        for (int m = 0; m < TAPS; m++) {
            const int i = m / KS, j = m % KS;
            u64 nd0 = s_dup[(c * SM_H + ry + i    ) * SM_W + tx + j];   // (v,v) via LDS.64
            u64 nd1 = s_dup[(c * SM_H + ry + i + 1) * SM_W + tx + j];
            const u64* wp = &s_w2[(c * TAPS + m) * NKP];
#pragma unroll
            for (int q = 0; q < NKP; q++) {
                u64 wv = wp[q];                  // one LDS.64: two distinct weights
                ffma2(wacc[0][q], wv, nd0);
                ffma2(wacc[1][q], wv, nd1);
            }
        }
    }

    // ---- Pass 2: fold k-pairs into packed output (lane-split sums), horizontal-add
    float* ob = out + (size_t)b * CCH * H * W;
    const int h = h0 + ry;
    const int w = w0 + tx;

#pragma unroll
    for (int c = 0; c < CCH; c++) {
        u64 acc[RPT];
#pragma unroll
        for (int p = 0; p < RPT; p++) {
            float rlo, rhi;
            unpack2(s_dup[(c * SM_H + ry + p + HALO) * SM_W + tx + HALO], rlo, rhi);
            acc[p] = pack2(rlo, 0.0f);           // residual in lane0
        }

#pragma unroll
        for (int q = 0; q < NKP; q++) {
            const int k0 = 2 * q, k1 = k0 + 1;
            const int i0 = k0 / KS, j0 = k0 % KS;
            const int i1 = (k1 < TAPS) ? k1 / KS : 0;
            const int j1 = (k1 < TAPS) ? k1 % KS : 0;
#pragma unroll
            for (int p = 0; p < RPT; p++) {
                float n0, n0x, n1x, n1;
                unpack2(s_dup[(c * SM_H + ry + p + i0) * SM_W + tx + j0], n0, n0x);
                if (k1 < TAPS) {
                    unpack2(s_dup[(c * SM_H + ry + p + i1) * SM_W + tx + j1], n1x, n1);
                } else {
                    n1 = 0.0f;
                }
                ffma2(acc[p], wacc[p][q], pack2(n0, n1));
            }
        }

        float* op = ob + (size_t)c * H * W + (size_t)h * W + w;
#pragma unroll
        for (int p = 0; p < RPT; p++) {
            float lo, hi;
            unpack2(acc[p], lo, hi);
            op[(size_t)p * W] = lo + hi;
        }
    }
}

extern "C" void kernel_launch(void* const* d_in, const int* in_sizes, int n_in,
                              void* d_out, int out_size)
{
    const float* x  = (const float*)d_in[0];
    const float* cw = (const float*)d_in[1];
    const float* cb = (const float*)d_in[2];
    float* out      = (float*)d_out;

    const int H = 256, W = 256;
    const int B = in_sizes[0] / (CCH * H * W);   // 16

    dim3 grid(W / TILE_W, H / TILE_H, B);        // (8, 16, 16) = 2048 blocks
    ho_kpair6_kernel<<<grid, NTHREADS>>>(x, cw, cb, out, H, W);
}

// round 15
// speedup vs baseline: 2.4470x; 1.2680x over previous
#include <cuda_runtime.h>

#define KS     5
#define TAPS   25
#define NKP    13          // k-pairs (k=25: pair 12 lane1 zero-padded)
#define CCH    3
#define HALO   2
#define TILE_W 32
#define TILE_H 16
#define RPT    2           // pixels (rows) per thread
#define SM_W   (TILE_W + 2*HALO)   // 36
#define SM_H   (TILE_H + 2*HALO)   // 20
#define NTHREADS 256

typedef unsigned long long u64;

__device__ __forceinline__ u64 pack2(float lo, float hi) {
    u64 r;
    asm("mov.b64 %0, {%1, %2};" : "=l"(r) : "f"(lo), "f"(hi));
    return r;
}
__device__ __forceinline__ void unpack2(u64 v, float& lo, float& hi) {
    asm("mov.b64 {%0, %1}, %2;" : "=f"(lo), "=f"(hi) : "l"(v));
}
__device__ __forceinline__ void ffma2(u64& d, u64 a, u64 b) {
    asm("fma.rn.f32x2 %0, %1, %2, %0;" : "+l"(d) : "l"(a), "l"(b));
}
__device__ __forceinline__ const float& st_at(const float* st, int c, int r, int col) {
    return st[(c * SM_H + r) * SM_W + col];
}

__global__ void __launch_bounds__(NTHREADS, 2)
ho_kpair7_kernel(const float* __restrict__ x,
                 const float* __restrict__ cw,   // [25][3][5][5]
                 const float* __restrict__ cb,   // [25]
                 float* __restrict__ out,
                 int H, int W)
{
    __shared__ float s_tile[CCH * SM_H * SM_W];       // 2160 f = 8.6 KB
    __shared__ u64   s_w2[CCH * TAPS * NKP];          // [(c*25+m)*13+kp] = 7.8 KB
    __shared__ u64   s_b2[NKP];

    const int tid = threadIdx.x;

    // Stage weights as k-pairs: s_w2[(c*25+m)*13+kp] = (cw[2kp][c][m], cw[2kp+1][c][m])
    for (int idx = tid; idx < CCH * TAPS * NKP; idx += NTHREADS) {
        int c   = idx / (TAPS * NKP);
        int rem = idx % (TAPS * NKP);
        int m   = rem / NKP;
        int kp  = rem % NKP;
        int k0 = 2 * kp, k1 = k0 + 1;
        float w0 = cw[(k0 * CCH + c) * TAPS + m];
        float w1 = (k1 < TAPS) ? cw[(k1 * CCH + c) * TAPS + m] : 0.0f;
        s_w2[idx] = pack2(w0, w1);
    }
    if (tid < NKP) {
        int k0 = 2 * tid, k1 = k0 + 1;
        s_b2[tid] = pack2(cb[k0], (k1 < TAPS) ? cb[k1] : 0.0f);
    }

    const int b  = blockIdx.z;
    const int h0 = blockIdx.y * TILE_H;
    const int w0 = blockIdx.x * TILE_W;
    const float* xb = x + (size_t)b * CCH * H * W;

    // Stage input tile + halo (zero-padded at borders)
    for (int i = tid; i < CCH * SM_H * SM_W; i += NTHREADS) {
        int c   = i / (SM_H * SM_W);
        int r   = (i / SM_W) % SM_H;
        int col = i % SM_W;
        int hh = h0 + r   - HALO;
        int ww = w0 + col - HALO;
        float v = 0.0f;
        if (hh >= 0 && hh < H && ww >= 0 && ww < W)
            v = xb[(size_t)c * H * W + (size_t)hh * W + ww];
        s_tile[(c * SM_H + r) * SM_W + col] = v;
    }
    __syncthreads();

    const int tx = tid & 31;          // 0..31
    const int ty = tid >> 5;          // 0..7
    const int ry = ty * RPT;          // top pixel's tile-local row

    // ---- Pass 1: dynamic weights packed along k:
    //      wacc[p][kp] = (w_{2kp}(pixel p), w_{2kp+1}(pixel p))
    u64 wacc[RPT][NKP];
#pragma unroll
    for (int p = 0; p < RPT; p++)
#pragma unroll
        for (int q = 0; q < NKP; q++)
            wacc[p][q] = s_b2[q];

#pragma unroll
    for (int c = 0; c < CCH; c++) {
#pragma unroll
        for (int m = 0; m < TAPS; m++) {
            const int i = m / KS, j = m % KS;
            float v0 = st_at(s_tile, c, ry + i,     tx + j);
            float v1 = st_at(s_tile, c, ry + i + 1, tx + j);
            u64 nd0 = pack2(v0, v0);
            u64 nd1 = pack2(v1, v1);

            // Batch ALL 13 weight loads first (MLP=13 LDS.64 in flight),
            // then the 26 independent FFMA2s absorb the latency.
            const u64* wp = &s_w2[(c * TAPS + m) * NKP];
            u64 wv[NKP];
#pragma unroll
            for (int q = 0; q < NKP; q++)
                wv[q] = wp[q];
#pragma unroll
            for (int q = 0; q < NKP; q++) {
                ffma2(wacc[0][q], wv[q], nd0);
                ffma2(wacc[1][q], wv[q], nd1);
            }
        }
    }

    // ---- Pass 2: fold k-pairs into packed output (lane-split sums), horizontal-add
    float* ob = out + (size_t)b * CCH * H * W;
    const int h = h0 + ry;
    const int w = w0 + tx;

#pragma unroll
    for (int c = 0; c < CCH; c++) {
        u64 acc[RPT];
#pragma unroll
        for (int p = 0; p < RPT; p++)
            acc[p] = pack2(st_at(s_tile, c, ry + p + HALO, tx + HALO), 0.0f);  // residual lane0

#pragma unroll
        for (int q = 0; q < NKP; q++) {
            const int k0 = 2 * q, k1 = k0 + 1;
            const int i0 = k0 / KS, j0 = k0 % KS;
            const int i1 = (k1 < TAPS) ? k1 / KS : 0;
            const int j1 = (k1 < TAPS) ? k1 % KS : 0;
#pragma unroll
            for (int p = 0; p < RPT; p++) {
                float n0 = st_at(s_tile, c, ry + p + i0, tx + j0);
                float n1 = (k1 < TAPS) ? st_at(s_tile, c, ry + p + i1, tx + j1) : 0.0f;
                ffma2(acc[p], wacc[p][q], pack2(n0, n1));
            }
        }

        float* op = ob + (size_t)c * H * W + (size_t)h * W + w;
#pragma unroll
        for (int p = 0; p < RPT; p++) {
            float lo, hi;
            unpack2(acc[p], lo, hi);
            op[(size_t)p * W] = lo + hi;
        }
    }
}

extern "C" void kernel_launch(void* const* d_in, const int* in_sizes, int n_in,
                              void* d_out, int out_size)
{
    const float* x  = (const float*)d_in[0];
    const float* cw = (const float*)d_in[1];
    const float* cb = (const float*)d_in[2];
    float* out      = (float*)d_out;

    const int H = 256, W = 256;
    const int B = in_sizes[0] / (CCH * H * W);   // 16

    dim3 grid(W / TILE_W, H / TILE_H, B);        // (8, 16, 16) = 2048 blocks
    ho_kpair7_kernel<<<grid, NTHREADS>>>(x, cw, cb, out, H, W);
}